// round 16
// baseline (speedup 1.0000x reference)
#include <cuda_runtime.h>

// Shapes fixed by setup_inputs
#define B_ 64
#define T_ 4096
#define F_ 64
#define H_ 256
#define EPSV 1e-8f

// Chunked scan: lambda=0.5 -> 32-step warm-up error ~0.5^32.
#define CHUNK 64
#define NCHUNK (T_ / CHUNK)        // 64
#define WARM 32

#define NS (B_ * NCHUNK)           // 4096 scan blocks
#define NM 16                      // mse blocks
#define NB (NS + NM)

__device__ float g_part[NB];
__device__ unsigned int g_cnt = 0;

// fg reduction, octet layout: warp covers rows [warp*32, warp*32+32) in 8
// passes of 4 rows; lane -> (sub-row = lane>>3, col0 = lane&7); each lane
// issues 8 INDEPENDENT LDG.128 (MLP=8), tree-sum, 3-shfl octet reduce.
#define FG_REDUCE_OCTET()                                                     \
    {                                                                         \
        int sub = lane >> 3;                                                  \
        int col0 = lane & 7;                                                  \
        _Pragma("unroll")                                                     \
        for (int pass = 0; pass < 8; ++pass) {                                \
            int r = warp * 32 + pass * 4 + sub;                               \
            const float4* rp = fgb + (size_t)r * (H_ / 4) + col0;             \
            float4 a0 = rp[0],  a1 = rp[8],  a2 = rp[16], a3 = rp[24];        \
            float4 a4 = rp[32], a5 = rp[40], a6 = rp[48], a7 = rp[56];        \
            float s =                                                         \
              (((a0.x + a0.y) + (a0.z + a0.w)) + ((a1.x + a1.y) + (a1.z + a1.w))) + \
              (((a2.x + a2.y) + (a2.z + a2.w)) + ((a3.x + a3.y) + (a3.z + a3.w))) + \
              (((a4.x + a4.y) + (a4.z + a4.w)) + ((a5.x + a5.y) + (a5.z + a5.w))) + \
              (((a6.x + a6.y) + (a6.z + a6.w)) + ((a7.x + a7.y) + (a7.z + a7.w))); \
            s += __shfl_xor_sync(0xffffffffu, s, 1);                          \
            s += __shfl_xor_sync(0xffffffffu, s, 2);                          \
            s += __shfl_xor_sync(0xffffffffu, s, 4);                          \
            if (col0 == 0) fgsum_s[r] = s;                                    \
        }                                                                     \
    }

// ---------------------------------------------------------------------------
// Fused kernel with PHASE-ORDER PARITY (R15-proven) + octet-MLP fg phase:
//   even blocks: fg reduction -> scan (private acc)
//   odd  blocks: scan (per-t shfl into smem) -> fg -> dot
// At any instant ~half the resident blocks stream forget_gates with MLP=8
// while the other half run the latency-bound recurrence.
//  [NS, NB): MSE partial blocks. Last arriving block finalizes (threadfence).
// ---------------------------------------------------------------------------
__global__ void __launch_bounds__(64) k_main(const float* __restrict__ seq,
                                             const float4* __restrict__ fg,
                                             const float4* __restrict__ inp,
                                             const float4* __restrict__ tgt,
                                             float* __restrict__ out) {
    __shared__ float fgsum_s[CHUNK];
    __shared__ float ws[2][CHUNK];
    __shared__ float sh[2];
    __shared__ int is_last;

    int tid = threadIdx.x;
    int warp = tid >> 5, lane = tid & 31;

    if (blockIdx.x < NS) {
        int b = blockIdx.x / NCHUNK;
        int chunk = blockIdx.x % NCHUNK;
        int t0 = chunk * CHUNK;
        int first = (chunk == 0);
        int ts = first ? 1 : (t0 - WARM);
        const float* base = seq + (size_t)b * T_ * F_ + tid;
        const float4* fgb = fg + (size_t)(b * T_ + t0) * (H_ / 4);

        if ((blockIdx.x & 1) == 0) {
            // ================= EVEN: fg -> scan =================
            FG_REDUCE_OCTET()
            __syncthreads();

            float m = 0.f, v = EPSV, c = 0.f;
            float xl = __ldg(base + (size_t)(ts - 1) * F_);
            float acc = first ? fgsum_s[0] : 0.f;      // t=0 pad: irr==1
#pragma unroll 8
            for (int t = ts; t < t0; ++t) {
                float xt = __ldg(base + (size_t)t * F_);
                m = 0.5f * (m + xt);
                float d = xt - m;
                v = 0.5f * (v + d * d);
                c = 0.5f * (c + d * (xl - m));
                xl = xt;
            }
            int tb = first ? 1 : t0;
#pragma unroll 8
            for (int t = tb; t < t0 + CHUNK; ++t) {
                float xt = __ldg(base + (size_t)t * F_);
                m = 0.5f * (m + xt);
                float d = xt - m;
                v = 0.5f * (v + d * d);
                c = 0.5f * (c + d * (xl - m));
                xl = xt;
                float ac = c * rsqrtf(v * v + EPSV);
                acc += (1.0f - fabsf(ac)) * fgsum_s[t - t0];
            }
#pragma unroll
            for (int o = 16; o > 0; o >>= 1) acc += __shfl_xor_sync(0xffffffffu, acc, o);
            if (lane == 0) sh[warp] = acc;
            __syncthreads();
            if (tid == 0)
                g_part[blockIdx.x] = (sh[0] + sh[1]) * (0.5f / 4294967296.0f);
        } else {
            // ================= ODD: scan -> fg -> dot =================
            float m = 0.f, v = EPSV, c = 0.f;
            float xl = __ldg(base + (size_t)(ts - 1) * F_);
#pragma unroll 8
            for (int t = ts; t < t0; ++t) {            // warm-up
                float xt = __ldg(base + (size_t)t * F_);
                m = 0.5f * (m + xt);
                float d = xt - m;
                v = 0.5f * (v + d * d);
                c = 0.5f * (c + d * (xl - m));
                xl = xt;
            }
            if (first && tid < 2) ws[tid][0] = 0.f;    // t=0 pad: |ac| = 0
            int tb = first ? 1 : t0;
#pragma unroll 8
            for (int t = tb; t < t0 + CHUNK; ++t) {
                float xt = __ldg(base + (size_t)t * F_);
                m = 0.5f * (m + xt);
                float d = xt - m;
                v = 0.5f * (v + d * d);
                c = 0.5f * (c + d * (xl - m));
                xl = xt;
                float a = fabsf(c * rsqrtf(v * v + EPSV));
#pragma unroll
                for (int o = 16; o > 0; o >>= 1) a += __shfl_xor_sync(0xffffffffu, a, o);
                if (lane == 0) ws[warp][t - t0] = a;
            }
            __syncthreads();

            FG_REDUCE_OCTET()
            __syncthreads();

            // dot: thread tid owns timestep tid
            float acc = ((float)F_ - ws[0][tid] - ws[1][tid]) * fgsum_s[tid];
#pragma unroll
            for (int o = 16; o > 0; o >>= 1) acc += __shfl_xor_sync(0xffffffffu, acc, o);
            if (lane == 0) sh[warp] = acc;
            __syncthreads();
            if (tid == 0)
                g_part[blockIdx.x] = (sh[0] + sh[1]) * (0.5f / 4294967296.0f);
        }
    } else {
        // ================= MSE role =================
        int bid = blockIdx.x - NS;
        const int n4 = (B_ * T_) / 4;
        float acc = 0.f;
        for (int i = bid * 64 + tid; i < n4; i += NM * 64) {
            float4 a = inp[i], b = tgt[i];
            float dx = a.x - b.x, dy = a.y - b.y, dz = a.z - b.z, dw = a.w - b.w;
            acc += dx * dx + dy * dy + dz * dz + dw * dw;
        }
#pragma unroll
        for (int o = 16; o > 0; o >>= 1) acc += __shfl_xor_sync(0xffffffffu, acc, o);
        if (lane == 0) sh[warp] = acc;
        __syncthreads();
        if (tid == 0)
            g_part[blockIdx.x] = (sh[0] + sh[1]) * (1.0f / ((float)B_ * T_));
    }

    // ---- last-block finalize (threadfence reduction, graph-replay safe) ----
    if (tid == 0) {
        __threadfence();
        unsigned int t = atomicAdd(&g_cnt, 1u);
        is_last = (t == NB - 1);
    }
    __syncthreads();
    if (is_last) {
        double s = 0.0;
        for (int i = tid; i < NB; i += 64) s += (double)g_part[i];
#pragma unroll
        for (int o = 16; o > 0; o >>= 1) s += __shfl_xor_sync(0xffffffffu, s, o);
        __shared__ double sd[2];
        if (lane == 0) sd[warp] = s;
        __syncthreads();
        if (tid == 0) {
            out[0] = (float)(sd[0] + sd[1]);
            g_cnt = 0;                       // reset for next graph replay
        }
    }
}

// ---------------------------------------------------------------------------
extern "C" void kernel_launch(void* const* d_in, const int* in_sizes, int n_in,
                              void* d_out, int out_size) {
    const float* input  = (const float*)d_in[0];
    const float* target = (const float*)d_in[1];
    const float* seq    = (const float*)d_in[2];
    const float* fg     = (const float*)d_in[3];

    k_main<<<NB, 64>>>(seq, (const float4*)fg,
                       (const float4*)input, (const float4*)target,
                       (float*)d_out);
}

// round 17
// speedup vs baseline: 1.2232x; 1.2232x over previous
#include <cuda_runtime.h>

// Shapes fixed by setup_inputs
#define B_ 64
#define T_ 4096
#define F_ 64
#define H_ 256
#define EPSV 1e-8f

// Chunked scan: lambda=0.5 -> 16-step warm-up error ~0.5^16 ≈ 1.5e-5,
// two orders below the 1e-3 gate (R15 measured 6e-8 with WARM=32).
#define CHUNK 64
#define NCHUNK (T_ / CHUNK)        // 64
#define WARM 16

#define NS (B_ * NCHUNK)           // 4096 scan blocks
#define NM 16                      // mse blocks
#define NB (NS + NM)

__device__ float g_part[NB];
__device__ unsigned int g_cnt = 0;

// ---------------------------------------------------------------------------
// Fused kernel with PHASE-ORDER PARITY (R15-proven structure, 32 regs):
//   even blocks: fg reduction -> scan (private acc)
//   odd  blocks: scan (per-t shfl into smem) -> fg -> dot
// At any wall-clock instant ~half the resident blocks stream forget_gates
// (DRAM-bound) while the other half run the recurrence (latency-bound).
//  [NS, NB): MSE partial blocks. Last arriving block finalizes (threadfence).
// ---------------------------------------------------------------------------
__global__ void __launch_bounds__(64) k_main(const float* __restrict__ seq,
                                             const float4* __restrict__ fg,
                                             const float4* __restrict__ inp,
                                             const float4* __restrict__ tgt,
                                             float* __restrict__ out) {
    __shared__ float fgsum_s[CHUNK];
    __shared__ float ws[2][CHUNK];
    __shared__ float sh[2];
    __shared__ int is_last;

    int tid = threadIdx.x;
    int warp = tid >> 5, lane = tid & 31;

    if (blockIdx.x < NS) {
        int b = blockIdx.x / NCHUNK;
        int chunk = blockIdx.x % NCHUNK;
        int t0 = chunk * CHUNK;
        int first = (chunk == 0);
        int ts = first ? 1 : (t0 - WARM);
        const float* base = seq + (size_t)b * T_ * F_ + tid;
        const float4* fgb = fg + (size_t)(b * T_ + t0) * (H_ / 4);

        if ((blockIdx.x & 1) == 0) {
            // ================= EVEN: fg -> scan (R6/R15 path) =================
            int r0 = warp * (CHUNK / 2);
            for (int r = r0; r < r0 + CHUNK / 2; r += 2) {
                const float4* ra = fgb + (size_t)r * (H_ / 4);
                const float4* rb = ra + (H_ / 4);
                float4 a0 = ra[lane], a1 = ra[lane + 32];
                float4 b0 = rb[lane], b1 = rb[lane + 32];
                float s0 = (a0.x + a0.y) + (a0.z + a0.w) + (a1.x + a1.y) + (a1.z + a1.w);
                float s1 = (b0.x + b0.y) + (b0.z + b0.w) + (b1.x + b1.y) + (b1.z + b1.w);
#pragma unroll
                for (int o = 16; o > 0; o >>= 1) {
                    s0 += __shfl_xor_sync(0xffffffffu, s0, o);
                    s1 += __shfl_xor_sync(0xffffffffu, s1, o);
                }
                if (lane == 0) { fgsum_s[r] = s0; fgsum_s[r + 1] = s1; }
            }
            __syncthreads();

            float m = 0.f, v = EPSV, c = 0.f;
            float xl = __ldg(base + (size_t)(ts - 1) * F_);
            float acc = first ? fgsum_s[0] : 0.f;      // t=0 pad: irr==1
#pragma unroll 8
            for (int t = ts; t < t0; ++t) {
                float xt = __ldg(base + (size_t)t * F_);
                m = 0.5f * (m + xt);
                float d = xt - m;
                v = 0.5f * (v + d * d);
                c = 0.5f * (c + d * (xl - m));
                xl = xt;
            }
            int tb = first ? 1 : t0;
#pragma unroll 8
            for (int t = tb; t < t0 + CHUNK; ++t) {
                float xt = __ldg(base + (size_t)t * F_);
                m = 0.5f * (m + xt);
                float d = xt - m;
                v = 0.5f * (v + d * d);
                c = 0.5f * (c + d * (xl - m));
                xl = xt;
                float ac = c * rsqrtf(v * v + EPSV);
                acc += (1.0f - fabsf(ac)) * fgsum_s[t - t0];
            }
#pragma unroll
            for (int o = 16; o > 0; o >>= 1) acc += __shfl_xor_sync(0xffffffffu, acc, o);
            if (lane == 0) sh[warp] = acc;
            __syncthreads();
            if (tid == 0)
                g_part[blockIdx.x] = (sh[0] + sh[1]) * (0.5f / 4294967296.0f);
        } else {
            // ================= ODD: scan -> fg -> dot =================
            float m = 0.f, v = EPSV, c = 0.f;
            float xl = __ldg(base + (size_t)(ts - 1) * F_);
#pragma unroll 8
            for (int t = ts; t < t0; ++t) {            // warm-up
                float xt = __ldg(base + (size_t)t * F_);
                m = 0.5f * (m + xt);
                float d = xt - m;
                v = 0.5f * (v + d * d);
                c = 0.5f * (c + d * (xl - m));
                xl = xt;
            }
            if (first && tid < 2) ws[tid][0] = 0.f;    // t=0 pad: |ac| = 0
            int tb = first ? 1 : t0;
#pragma unroll 8
            for (int t = tb; t < t0 + CHUNK; ++t) {
                float xt = __ldg(base + (size_t)t * F_);
                m = 0.5f * (m + xt);
                float d = xt - m;
                v = 0.5f * (v + d * d);
                c = 0.5f * (c + d * (xl - m));
                xl = xt;
                float a = fabsf(c * rsqrtf(v * v + EPSV));
#pragma unroll
                for (int o = 16; o > 0; o >>= 1) a += __shfl_xor_sync(0xffffffffu, a, o);
                if (lane == 0) ws[warp][t - t0] = a;
            }
            __syncthreads();

            // fg reduction (same layout as even path)
            int r0 = warp * (CHUNK / 2);
            for (int r = r0; r < r0 + CHUNK / 2; r += 2) {
                const float4* ra = fgb + (size_t)r * (H_ / 4);
                const float4* rb = ra + (H_ / 4);
                float4 a0 = ra[lane], a1 = ra[lane + 32];
                float4 b0 = rb[lane], b1 = rb[lane + 32];
                float s0 = (a0.x + a0.y) + (a0.z + a0.w) + (a1.x + a1.y) + (a1.z + a1.w);
                float s1 = (b0.x + b0.y) + (b0.z + b0.w) + (b1.x + b1.y) + (b1.z + b1.w);
#pragma unroll
                for (int o = 16; o > 0; o >>= 1) {
                    s0 += __shfl_xor_sync(0xffffffffu, s0, o);
                    s1 += __shfl_xor_sync(0xffffffffu, s1, o);
                }
                if (lane == 0) { fgsum_s[r] = s0; fgsum_s[r + 1] = s1; }
            }
            __syncthreads();

            // dot: thread tid owns timestep tid
            float acc = ((float)F_ - ws[0][tid] - ws[1][tid]) * fgsum_s[tid];
#pragma unroll
            for (int o = 16; o > 0; o >>= 1) acc += __shfl_xor_sync(0xffffffffu, acc, o);
            if (lane == 0) sh[warp] = acc;
            __syncthreads();
            if (tid == 0)
                g_part[blockIdx.x] = (sh[0] + sh[1]) * (0.5f / 4294967296.0f);
        }
    } else {
        // ================= MSE role =================
        int bid = blockIdx.x - NS;
        const int n4 = (B_ * T_) / 4;
        float acc = 0.f;
        for (int i = bid * 64 + tid; i < n4; i += NM * 64) {
            float4 a = inp[i], b = tgt[i];
            float dx = a.x - b.x, dy = a.y - b.y, dz = a.z - b.z, dw = a.w - b.w;
            acc += dx * dx + dy * dy + dz * dz + dw * dw;
        }
#pragma unroll
        for (int o = 16; o > 0; o >>= 1) acc += __shfl_xor_sync(0xffffffffu, acc, o);
        if (lane == 0) sh[warp] = acc;
        __syncthreads();
        if (tid == 0)
            g_part[blockIdx.x] = (sh[0] + sh[1]) * (1.0f / ((float)B_ * T_));
    }

    // ---- last-block finalize (threadfence reduction, graph-replay safe) ----
    if (tid == 0) {
        __threadfence();
        unsigned int t = atomicAdd(&g_cnt, 1u);
        is_last = (t == NB - 1);
    }
    __syncthreads();
    if (is_last) {
        double s = 0.0;
        for (int i = tid; i < NB; i += 64) s += (double)g_part[i];
#pragma unroll
        for (int o = 16; o > 0; o >>= 1) s += __shfl_xor_sync(0xffffffffu, s, o);
        __shared__ double sd[2];
        if (lane == 0) sd[warp] = s;
        __syncthreads();
        if (tid == 0) {
            out[0] = (float)(sd[0] + sd[1]);
            g_cnt = 0;                       // reset for next graph replay
        }
    }
}

// ---------------------------------------------------------------------------
extern "C" void kernel_launch(void* const* d_in, const int* in_sizes, int n_in,
                              void* d_out, int out_size) {
    const float* input  = (const float*)d_in[0];
    const float* target = (const float*)d_in[1];
    const float* seq    = (const float*)d_in[2];
    const float* fg     = (const float*)d_in[3];

    k_main<<<NB, 64>>>(seq, (const float4*)fg,
                       (const float4*)input, (const float4*)target,
                       (float*)d_out);
}